// round 5
// baseline (speedup 1.0000x reference)
#include <cuda_runtime.h>
#include <cuda_bf16.h>
#include <cstdint>
#include <math.h>

// Problem constants
#define LL 128
#define BB 512
#define DD 512
#define SS 128
#define LB (LL * BB)   // 65536

// -------- device scratch --------
__device__ __align__(16) float          g_colbias[SS];
__device__ __align__(16) float          g_rvar[DD];
__device__ __align__(16) __nv_bfloat16  g_Mv[SS * DD];          // mu/var bf16, [s][d]
__device__ __align__(16) __nv_bfloat16  g_At[SS * SS];          // A transposed: At[j][i] = A[i][j], bf16
// E in mma-fragment layout, lane-major: [((l*32 + btile)*16 + n)*32 + lane]
__device__ __align__(16) uint2          g_Efrag[(size_t)LL * 32 * 16 * 32]; // 16 MB
__device__ __align__(16) float          g_dmaxT[BB * LL];       // dmax transposed: [b][l]
__device__ __align__(16) float          g_perb[BB];

#define LOG2PI 1.8378770664093453f
#define LOGPI_INIT (-4.852030263919617f)   // -log(128)

// ---- fast exp on the FMA pipe (x <= 0 expected; flushes below -80) ----
__device__ __forceinline__ float fexp(float x) {
    float t = fmaf(x, 1.4426950408889634f, 12582912.0f);
    int   ni = __float_as_int(t) - 0x4B400000;
    float n  = t - 12582912.0f;
    float f  = fmaf(x, 1.4426950408889634f, -n);
    float r  = 0.0013333558f;
    r = fmaf(r, f, 0.0096181291f);
    r = fmaf(r, f, 0.0555041087f);
    r = fmaf(r, f, 0.2402264689f);
    r = fmaf(r, f, 0.6931471806f);
    r = fmaf(r, f, 1.0f);
    float res = __int_as_float(__float_as_int(r) + (ni << 23));
    return (x > -80.0f) ? res : 0.0f;
}

__device__ __forceinline__ uint32_t pk(__nv_bfloat162 v) { return *reinterpret_cast<uint32_t*>(&v); }
__device__ __forceinline__ __nv_bfloat162 upk(uint32_t v) { return *reinterpret_cast<__nv_bfloat162*>(&v); }
__device__ __forceinline__ uint32_t smem_u32(const void* p) {
    return (uint32_t)__cvta_generic_to_shared(p);
}

__device__ __forceinline__ void mma_bf16(float& c0, float& c1, float& c2, float& c3,
                                         uint32_t a0, uint32_t a1, uint32_t a2, uint32_t a3,
                                         uint32_t b0, uint32_t b1) {
    asm volatile(
        "mma.sync.aligned.m16n8k16.row.col.f32.bf16.bf16.f32 "
        "{%0,%1,%2,%3}, {%4,%5,%6,%7}, {%8,%9}, {%0,%1,%2,%3};\n"
        : "+f"(c0), "+f"(c1), "+f"(c2), "+f"(c3)
        : "r"(a0), "r"(a1), "r"(a2), "r"(a3), "r"(b0), "r"(b1));
}

__device__ __forceinline__ void ldmx4(uint32_t& r0, uint32_t& r1, uint32_t& r2, uint32_t& r3,
                                      uint32_t addr) {
    asm volatile("ldmatrix.sync.aligned.m8n8.x4.shared.b16 {%0,%1,%2,%3}, [%4];"
                 : "=r"(r0), "=r"(r1), "=r"(r2), "=r"(r3) : "r"(addr));
}

// =====================================================================
// Kernel 1: preprocessing (1 block, 512 threads)
// =====================================================================
__global__ void prep_kernel(const float* __restrict__ tparams,
                            const float* __restrict__ means,
                            const float* __restrict__ var) {
    __shared__ float sred[512];
    int t = threadIdx.x;

    float v = var[t];
    g_rvar[t] = 1.0f / v;
    sred[t] = logf(v);
    __syncthreads();
    for (int off = 256; off > 0; off >>= 1) {
        if (t < off) sred[t] += sred[t + off];
        __syncthreads();
    }
    float slv = sred[0];
    float c = -256.0f * LOG2PI - 0.5f * slv;

    int q   = t & 3;      // 0..3
    int grp = t >> 2;     // 0..127  (row i)

    // col bias
    {
        float mq = 0.f;
        for (int d = q; d < DD; d += 4) {
            float m = means[grp * DD + d];
            mq += m * m * g_rvar[d];
        }
        mq += __shfl_xor_sync(0xffffffffu, mq, 1);
        mq += __shfl_xor_sync(0xffffffffu, mq, 2);
        if (q == 0) g_colbias[grp] = c - 0.5f * mq;
    }

    // At[j][i] = exp(tparams[i][j] - lse_j'(tparams[i][:]))
    {
        float mx = -1e30f;
        for (int jj = q; jj < SS; jj += 4) mx = fmaxf(mx, tparams[grp * SS + jj]);
        mx = fmaxf(mx, __shfl_xor_sync(0xffffffffu, mx, 1));
        mx = fmaxf(mx, __shfl_xor_sync(0xffffffffu, mx, 2));
        float se = 0.f;
        for (int jj = q; jj < SS; jj += 4) se += __expf(tparams[grp * SS + jj] - mx);
        se += __shfl_xor_sync(0xffffffffu, se, 1);
        se += __shfl_xor_sync(0xffffffffu, se, 2);
        float lse = mx + __logf(se);
        for (int jj = q; jj < SS; jj += 4)
            g_At[jj * SS + grp] = __float2bfloat16(__expf(tparams[grp * SS + jj] - lse));
    }

    // Mv = mu / var in bf16
    for (int idx = t; idx < SS * DD; idx += 512) {
        int d = idx & (DD - 1);
        g_Mv[idx] = __float2bfloat16(means[idx] * g_rvar[d]);
    }
}

// =====================================================================
// Kernel 2: fused density GEMM -> E (fragment layout, bf16) + dmaxT
// =====================================================================
#define SMSTRIDE 72

__global__ __launch_bounds__(256) void density_kernel(const float* __restrict__ sents) {
    __shared__ __align__(16) __nv_bfloat16 sA[128 * SMSTRIDE];
    __shared__ __align__(16) __nv_bfloat16 sB[128 * SMSTRIDE];
    __shared__ __align__(16) float srv[DD];
    __shared__ float sXQ[128];
    __shared__ float scb[128];

    int tid  = threadIdx.x;
    int warp = tid >> 5, lane = tid & 31;
    int g = lane >> 2, tg = lane & 3;
    int mbase = blockIdx.x * 128;

    for (int i = tid; i < DD; i += 256) srv[i] = g_rvar[i];
    if (tid < 128) scb[tid] = g_colbias[tid];

    float acc[16][4];
#pragma unroll
    for (int n = 0; n < 16; ++n)
#pragma unroll
        for (int k = 0; k < 4; ++k) acc[n][k] = 0.f;

    float xqp[8];
#pragma unroll
    for (int k = 0; k < 8; ++k) xqp[k] = 0.f;

    __syncthreads();

    for (int ko = 0; ko < 8; ++ko) {
#pragma unroll
        for (int k = 0; k < 8; ++k) {
            int idx = tid + k * 256;
            int r = idx >> 4, c4 = idx & 15;
            float4 x = *reinterpret_cast<const float4*>(
                &sents[(size_t)(mbase + r) * DD + ko * 64 + c4 * 4]);
            __nv_bfloat162 p0 = __float22bfloat162_rn(make_float2(x.x, x.y));
            __nv_bfloat162 p1 = __float22bfloat162_rn(make_float2(x.z, x.w));
            uint2 pkk;
            pkk.x = pk(p0);
            pkk.y = pk(p1);
            *reinterpret_cast<uint2*>(&sA[r * SMSTRIDE + c4 * 4]) = pkk;

            float4 rv = *reinterpret_cast<const float4*>(&srv[ko * 64 + c4 * 4]);
            xqp[k] += x.x * x.x * rv.x + x.y * x.y * rv.y
                    + x.z * x.z * rv.z + x.w * x.w * rv.w;
        }
#pragma unroll
        for (int k = 0; k < 4; ++k) {
            int idx = tid + k * 256;
            int r = idx >> 3, c8 = idx & 7;
            uint4 vb = *reinterpret_cast<const uint4*>(&g_Mv[(size_t)r * DD + ko * 64 + c8 * 8]);
            *reinterpret_cast<uint4*>(&sB[r * SMSTRIDE + c8 * 8]) = vb;
        }
        __syncthreads();

#pragma unroll
        for (int ks = 0; ks < 4; ++ks) {
            int k0 = ks * 16 + tg * 2;
            uint32_t a0 = *reinterpret_cast<const uint32_t*>(&sA[(warp * 16 + g)     * SMSTRIDE + k0]);
            uint32_t a1 = *reinterpret_cast<const uint32_t*>(&sA[(warp * 16 + g + 8) * SMSTRIDE + k0]);
            uint32_t a2 = *reinterpret_cast<const uint32_t*>(&sA[(warp * 16 + g)     * SMSTRIDE + k0 + 8]);
            uint32_t a3 = *reinterpret_cast<const uint32_t*>(&sA[(warp * 16 + g + 8) * SMSTRIDE + k0 + 8]);
#pragma unroll
            for (int n = 0; n < 16; ++n) {
                uint32_t b0 = *reinterpret_cast<const uint32_t*>(&sB[(n * 8 + g) * SMSTRIDE + k0]);
                uint32_t b1 = *reinterpret_cast<const uint32_t*>(&sB[(n * 8 + g) * SMSTRIDE + k0 + 8]);
                mma_bf16(acc[n][0], acc[n][1], acc[n][2], acc[n][3], a0, a1, a2, a3, b0, b1);
            }
        }
        __syncthreads();
    }

    // xq reduce
#pragma unroll
    for (int k = 0; k < 8; ++k) {
        float s = xqp[k];
        s += __shfl_xor_sync(0xffffffffu, s, 1);
        s += __shfl_xor_sync(0xffffffffu, s, 2);
        s += __shfl_xor_sync(0xffffffffu, s, 4);
        s += __shfl_xor_sync(0xffffffffu, s, 8);
        if ((lane & 15) == 0) sXQ[(tid >> 4) + k * 16] = -0.5f * s;
    }
    __syncthreads();

    int r0l = warp * 16 + g;
    int r1l = r0l + 8;
    int r0 = mbase + r0l, r1 = mbase + r1l;
    float xq0 = sXQ[r0l], xq1 = sXQ[r1l];

    float mx0 = -1e30f, mx1 = -1e30f;
#pragma unroll
    for (int n = 0; n < 16; ++n) {
        int col = n * 8 + tg * 2;
        float cb0 = scb[col], cb1 = scb[col + 1];
        acc[n][0] += cb0; acc[n][1] += cb1;
        acc[n][2] += cb0; acc[n][3] += cb1;
        mx0 = fmaxf(mx0, fmaxf(acc[n][0], acc[n][1]));
        mx1 = fmaxf(mx1, fmaxf(acc[n][2], acc[n][3]));
    }
    mx0 = fmaxf(mx0, __shfl_xor_sync(0xffffffffu, mx0, 1));
    mx0 = fmaxf(mx0, __shfl_xor_sync(0xffffffffu, mx0, 2));
    mx1 = fmaxf(mx1, __shfl_xor_sync(0xffffffffu, mx1, 1));
    mx1 = fmaxf(mx1, __shfl_xor_sync(0xffffffffu, mx1, 2));

    // E fragment write, lane-major: [((l*32+btile)*16 + n)*32 + lane]
    int b = r0 & (BB - 1);
    int l = r0 >> 9;
    int btile = b >> 4;
    uint2* eout = &g_Efrag[((size_t)(l * 32 + btile) * 16) * 32 + lane];
#pragma unroll
    for (int n = 0; n < 16; ++n) {
        __nv_bfloat162 e01 = __floats2bfloat162_rn(fexp(acc[n][0] - mx0), fexp(acc[n][1] - mx0));
        __nv_bfloat162 e23 = __floats2bfloat162_rn(fexp(acc[n][2] - mx1), fexp(acc[n][3] - mx1));
        eout[n * 32] = make_uint2(pk(e01), pk(e23));
    }
    if (tg == 0) {
        g_dmaxT[(size_t)b * LL + l]       = mx0 + xq0;
        g_dmaxT[(size_t)(b + 8) * LL + l] = mx1 + xq1;
    }
}

// =====================================================================
// Kernel 3: forward recurrence — warp-independent tensor-core version.
// 32 CTAs x 32 threads; each warp owns 16 batches for all 127 steps.
// p' = E .* (p @ A) as m16n128k128 mma; acc->a-frag repack register-local.
// NO barriers, NO cross-lane traffic in the step loop.
// =====================================================================
#define ATSTRIDE 136   // bf16 elems per padded row (272 B)

__global__ __launch_bounds__(32) void recur_kernel(const float* __restrict__ masks) {
    __shared__ __align__(16) __nv_bfloat16 sAt[SS * ATSTRIDE];  // 34816 B
    __shared__ float sdmax[LL * 16];                             // 8192 B
    __shared__ unsigned char smk[LL * 16];                       // 2048 B

    int lane  = threadIdx.x;
    int btile = blockIdx.x;          // 0..31
    int g = lane >> 2;               // 0..7

    // stage A^T with padding
    {
        const uint4* src = reinterpret_cast<const uint4*>(g_At);   // 2048 uint4
        for (int idx = lane; idx < 2048; idx += 32) {
            int j = idx >> 4, c = idx & 15;
            *reinterpret_cast<uint4*>(&sAt[j * ATSTRIDE + c * 8]) = src[idx];
        }
    }
    // stage dmax + masks for this warp's 16 batches
    for (int idx = lane; idx < 2048; idx += 32) {
        int bi = idx >> 7, l = idx & 127;
        sdmax[l * 16 + bi] = g_dmaxT[(size_t)(btile * 16 + bi) * LL + l];
        smk[l * 16 + bi]   = (masks[l * BB + btile * 16 + bi] >= 0.5f) ? 1 : 0;
    }
    __syncwarp();

    // per-lane ldmatrix base (x4: m0 = n0-7/k0-7, m1 = n0-7/k8-15, m2 = n8-15/k0-7, m3 = n8-15/k8-15)
    int q = lane >> 3, r = lane & 7;
    int rowb = ((q & 2) ? 8 : 0) + r;
    int kofs = (q & 1) ? 8 : 0;
    uint32_t lm_base = smem_u32(&sAt[rowb * ATSTRIDE + kofs]);

    const uint2* __restrict__ Eb = g_Efrag + (size_t)btile * 512 + lane;  // + l*16384 + n*32

    // init p = E[0] as a-frags: af[kt*4+{0,1,2,3}] = {row g klow, row g+8 klow, row g khigh, row g+8 khigh}
    uint32_t af[32];
#pragma unroll
    for (int n = 0; n < 16; ++n) {
        uint2 e = Eb[n * 32];
        af[(n >> 1) * 4 + (n & 1) * 2]     = e.x;
        af[(n >> 1) * 4 + (n & 1) * 2 + 1] = e.y;
    }
    float Mg = LOGPI_INIT + sdmax[g];
    float Mh = LOGPI_INIT + sdmax[g + 8];

    float acc[16][4];
#pragma unroll
    for (int n = 0; n < 16; ++n)
#pragma unroll
        for (int k = 0; k < 4; ++k) acc[n][k] = 0.f;

    for (int l = 1; l < LL; ++l) {
        // prefetch E fragments for this step (coalesced uint2 loads, no aliasing)
        const uint2* Ep = Eb + (size_t)l * 16384;
        uint2 ef[16];
#pragma unroll
        for (int n = 0; n < 16; ++n) ef[n] = Ep[n * 32];

        float dm0 = sdmax[l * 16 + g];
        float dm1 = sdmax[l * 16 + g + 8];
        int mk0 = smk[l * 16 + g];
        int mk1 = smk[l * 16 + g + 8];

#pragma unroll
        for (int n = 0; n < 16; ++n)
#pragma unroll
            for (int k = 0; k < 4; ++k) acc[n][k] = 0.f;

        // m16n128k128: 8 k-tiles x 8 n-pairs
#pragma unroll
        for (int kt = 0; kt < 8; ++kt) {
            uint32_t a0 = af[kt * 4 + 0], a1 = af[kt * 4 + 1];
            uint32_t a2 = af[kt * 4 + 2], a3 = af[kt * 4 + 3];
#pragma unroll
            for (int np = 0; np < 8; ++np) {
                uint32_t b0, b1, b2, b3;
                ldmx4(b0, b1, b2, b3, lm_base + np * (16 * ATSTRIDE * 2) + kt * 32);
                mma_bf16(acc[2 * np][0], acc[2 * np][1], acc[2 * np][2], acc[2 * np][3],
                         a0, a1, a2, a3, b0, b1);
                mma_bf16(acc[2 * np + 1][0], acc[2 * np + 1][1], acc[2 * np + 1][2], acc[2 * np + 1][3],
                         a0, a1, a2, a3, b2, b3);
            }
        }

        // epilogue: multiply by E, mask blend, periodic renorm, repack
#pragma unroll
        for (int nt = 0; nt < 16; ++nt) {
            float2 eg = __bfloat1622float2(upk(ef[nt].x));   // row g
            float2 eh = __bfloat1622float2(upk(ef[nt].y));   // row g+8
            float n0 = acc[nt][0] * eg.x, n1 = acc[nt][1] * eg.y;
            float n2 = acc[nt][2] * eh.x, n3 = acc[nt][3] * eh.y;
            if (!mk0) {
                float2 o = __bfloat1622float2(upk(af[(nt >> 1) * 4 + (nt & 1) * 2]));
                n0 = o.x; n1 = o.y;
            }
            if (!mk1) {
                float2 o = __bfloat1622float2(upk(af[(nt >> 1) * 4 + (nt & 1) * 2 + 1]));
                n2 = o.x; n3 = o.y;
            }
            acc[nt][0] = n0; acc[nt][1] = n1; acc[nt][2] = n2; acc[nt][3] = n3;
        }
        if (mk0) Mg += dm0;
        if (mk1) Mh += dm1;

        if ((l & 7) == 0) {
            float mgv = 1e-30f, mhv = 1e-30f;
#pragma unroll
            for (int nt = 0; nt < 16; ++nt) {
                mgv = fmaxf(mgv, fmaxf(acc[nt][0], acc[nt][1]));
                mhv = fmaxf(mhv, fmaxf(acc[nt][2], acc[nt][3]));
            }
            mgv = fmaxf(mgv, __shfl_xor_sync(0xffffffffu, mgv, 1));
            mgv = fmaxf(mgv, __shfl_xor_sync(0xffffffffu, mgv, 2));
            mhv = fmaxf(mhv, __shfl_xor_sync(0xffffffffu, mhv, 1));
            mhv = fmaxf(mhv, __shfl_xor_sync(0xffffffffu, mhv, 2));
            float rg = 1.f / mgv, rh = 1.f / mhv;
#pragma unroll
            for (int nt = 0; nt < 16; ++nt) {
                acc[nt][0] *= rg; acc[nt][1] *= rg;
                acc[nt][2] *= rh; acc[nt][3] *= rh;
            }
            Mg += __logf(mgv);
            Mh += __logf(mhv);
        }

#pragma unroll
        for (int nt = 0; nt < 16; ++nt) {
            int kt = nt >> 1, h = nt & 1;
            af[kt * 4 + h * 2]     = pk(__floats2bfloat162_rn(acc[nt][0], acc[nt][1]));
            af[kt * 4 + h * 2 + 1] = pk(__floats2bfloat162_rn(acc[nt][2], acc[nt][3]));
        }
    }

    // objective per batch: M + log(sum_j p_j)
    float Sg = 0.f, Sh = 0.f;
#pragma unroll
    for (int nt = 0; nt < 16; ++nt) {
        Sg += acc[nt][0] + acc[nt][1];
        Sh += acc[nt][2] + acc[nt][3];
    }
    Sg += __shfl_xor_sync(0xffffffffu, Sg, 1);
    Sg += __shfl_xor_sync(0xffffffffu, Sg, 2);
    Sh += __shfl_xor_sync(0xffffffffu, Sh, 1);
    Sh += __shfl_xor_sync(0xffffffffu, Sh, 2);
    Sg = fmaxf(Sg, 1e-37f);
    Sh = fmaxf(Sh, 1e-37f);
    if ((lane & 3) == 0) {
        g_perb[btile * 16 + g]     = Mg + __logf(Sg);
        g_perb[btile * 16 + g + 8] = Mh + __logf(Sh);
    }
}

// =====================================================================
// Kernel 4: deterministic final reduction over 512 batch rows
// =====================================================================
__global__ void finalize_kernel(float* __restrict__ out, int out_size) {
    __shared__ float s[256];
    int t = threadIdx.x;
    s[t] = g_perb[t] + g_perb[t + 256];
    __syncthreads();
    for (int off = 128; off > 0; off >>= 1) {
        if (t < off) s[t] += s[t + off];
        __syncthreads();
    }
    for (int i = t; i < out_size; i += 256)
        if (i != 0) out[i] = 0.f;   // jacobian_loss = 0
    if (t == 0) out[0] = s[0];
}

// =====================================================================
extern "C" void kernel_launch(void* const* d_in, const int* in_sizes, int n_in,
                              void* d_out, int out_size) {
    const float* sents   = (const float*)d_in[0];
    const float* masks   = (const float*)d_in[1];
    const float* tparams = (const float*)d_in[2];
    const float* means   = (const float*)d_in[3];
    const float* var     = (const float*)d_in[4];
    float* out = (float*)d_out;

    prep_kernel<<<1, 512>>>(tparams, means, var);
    density_kernel<<<LB / 128, 256>>>(sents);
    recur_kernel<<<32, 32>>>(masks);
    finalize_kernel<<<1, 256>>>(out, out_size);
}

// round 7
// speedup vs baseline: 1.2173x; 1.2173x over previous
#include <cuda_runtime.h>
#include <cuda_bf16.h>
#include <cstdint>
#include <math.h>

// Problem constants
#define LL 128
#define BB 512
#define DD 512
#define SS 128
#define LB (LL * BB)   // 65536

// -------- device scratch --------
__device__ __align__(16) float          g_colbias[SS];
__device__ __align__(16) float          g_rvar[DD];
__device__ __align__(16) __nv_bfloat16  g_Mv[SS * DD];          // mu/var bf16, [s][d]
__device__ __align__(16) __nv_bfloat16  g_At[SS * SS];          // A transposed: At[j][i] = A[i][j], bf16
// E in mma-fragment layout, lane-major: [((l*32 + btile)*16 + n)*32 + lane]
__device__ __align__(16) uint2          g_Efrag[(size_t)LL * 32 * 16 * 32]; // 16 MB
__device__ __align__(16) float          g_dmaxT[BB * LL];       // dmax transposed: [b][l]
__device__ __align__(16) float          g_perb[BB];

#define LOG2PI 1.8378770664093453f
#define LOGPI_INIT (-4.852030263919617f)   // -log(128)

// ---- fast exp on the FMA pipe (x <= 0 expected; flushes below -80) ----
__device__ __forceinline__ float fexp(float x) {
    float t = fmaf(x, 1.4426950408889634f, 12582912.0f);
    int   ni = __float_as_int(t) - 0x4B400000;
    float n  = t - 12582912.0f;
    float f  = fmaf(x, 1.4426950408889634f, -n);
    float r  = 0.0013333558f;
    r = fmaf(r, f, 0.0096181291f);
    r = fmaf(r, f, 0.0555041087f);
    r = fmaf(r, f, 0.2402264689f);
    r = fmaf(r, f, 0.6931471806f);
    r = fmaf(r, f, 1.0f);
    float res = __int_as_float(__float_as_int(r) + (ni << 23));
    return (x > -80.0f) ? res : 0.0f;
}

__device__ __forceinline__ uint32_t pk(__nv_bfloat162 v) { return *reinterpret_cast<uint32_t*>(&v); }
__device__ __forceinline__ __nv_bfloat162 upk(uint32_t v) { return *reinterpret_cast<__nv_bfloat162*>(&v); }
__device__ __forceinline__ uint32_t smem_u32(const void* p) {
    return (uint32_t)__cvta_generic_to_shared(p);
}

__device__ __forceinline__ void mma_bf16(float& c0, float& c1, float& c2, float& c3,
                                         uint32_t a0, uint32_t a1, uint32_t a2, uint32_t a3,
                                         uint32_t b0, uint32_t b1) {
    asm volatile(
        "mma.sync.aligned.m16n8k16.row.col.f32.bf16.bf16.f32 "
        "{%0,%1,%2,%3}, {%4,%5,%6,%7}, {%8,%9}, {%0,%1,%2,%3};\n"
        : "+f"(c0), "+f"(c1), "+f"(c2), "+f"(c3)
        : "r"(a0), "r"(a1), "r"(a2), "r"(a3), "r"(b0), "r"(b1));
}

__device__ __forceinline__ void ldmx4(uint32_t& r0, uint32_t& r1, uint32_t& r2, uint32_t& r3,
                                      uint32_t addr) {
    asm volatile("ldmatrix.sync.aligned.m8n8.x4.shared.b16 {%0,%1,%2,%3}, [%4];"
                 : "=r"(r0), "=r"(r1), "=r"(r2), "=r"(r3) : "r"(addr));
}

// =====================================================================
// Kernel 1: preprocessing (1 block, 512 threads)
// =====================================================================
__global__ void prep_kernel(const float* __restrict__ tparams,
                            const float* __restrict__ means,
                            const float* __restrict__ var) {
    __shared__ float sred[512];
    int t = threadIdx.x;

    float v = var[t];
    g_rvar[t] = 1.0f / v;
    sred[t] = logf(v);
    __syncthreads();
    for (int off = 256; off > 0; off >>= 1) {
        if (t < off) sred[t] += sred[t + off];
        __syncthreads();
    }
    float slv = sred[0];
    float c = -256.0f * LOG2PI - 0.5f * slv;

    int q   = t & 3;      // 0..3
    int grp = t >> 2;     // 0..127  (row i)

    // col bias
    {
        float mq = 0.f;
        for (int d = q; d < DD; d += 4) {
            float m = means[grp * DD + d];
            mq += m * m * g_rvar[d];
        }
        mq += __shfl_xor_sync(0xffffffffu, mq, 1);
        mq += __shfl_xor_sync(0xffffffffu, mq, 2);
        if (q == 0) g_colbias[grp] = c - 0.5f * mq;
    }

    // At[j][i] = exp(tparams[i][j] - lse_j'(tparams[i][:]))
    {
        float mx = -1e30f;
        for (int jj = q; jj < SS; jj += 4) mx = fmaxf(mx, tparams[grp * SS + jj]);
        mx = fmaxf(mx, __shfl_xor_sync(0xffffffffu, mx, 1));
        mx = fmaxf(mx, __shfl_xor_sync(0xffffffffu, mx, 2));
        float se = 0.f;
        for (int jj = q; jj < SS; jj += 4) se += __expf(tparams[grp * SS + jj] - mx);
        se += __shfl_xor_sync(0xffffffffu, se, 1);
        se += __shfl_xor_sync(0xffffffffu, se, 2);
        float lse = mx + __logf(se);
        for (int jj = q; jj < SS; jj += 4)
            g_At[jj * SS + grp] = __float2bfloat16(__expf(tparams[grp * SS + jj] - lse));
    }

    // Mv = mu / var in bf16
    for (int idx = t; idx < SS * DD; idx += 512) {
        int d = idx & (DD - 1);
        g_Mv[idx] = __float2bfloat16(means[idx] * g_rvar[d]);
    }
}

// =====================================================================
// Kernel 2: fused density GEMM -> E (fragment layout, bf16) + dmaxT
// =====================================================================
#define SMSTRIDE 72

__global__ __launch_bounds__(256) void density_kernel(const float* __restrict__ sents) {
    __shared__ __align__(16) __nv_bfloat16 sA[128 * SMSTRIDE];
    __shared__ __align__(16) __nv_bfloat16 sB[128 * SMSTRIDE];
    __shared__ __align__(16) float srv[DD];
    __shared__ float sXQ[128];
    __shared__ float scb[128];

    int tid  = threadIdx.x;
    int warp = tid >> 5, lane = tid & 31;
    int g = lane >> 2, tg = lane & 3;
    int mbase = blockIdx.x * 128;

    for (int i = tid; i < DD; i += 256) srv[i] = g_rvar[i];
    if (tid < 128) scb[tid] = g_colbias[tid];

    float acc[16][4];
#pragma unroll
    for (int n = 0; n < 16; ++n)
#pragma unroll
        for (int k = 0; k < 4; ++k) acc[n][k] = 0.f;

    float xqp[8];
#pragma unroll
    for (int k = 0; k < 8; ++k) xqp[k] = 0.f;

    __syncthreads();

    for (int ko = 0; ko < 8; ++ko) {
#pragma unroll
        for (int k = 0; k < 8; ++k) {
            int idx = tid + k * 256;
            int r = idx >> 4, c4 = idx & 15;
            float4 x = *reinterpret_cast<const float4*>(
                &sents[(size_t)(mbase + r) * DD + ko * 64 + c4 * 4]);
            __nv_bfloat162 p0 = __float22bfloat162_rn(make_float2(x.x, x.y));
            __nv_bfloat162 p1 = __float22bfloat162_rn(make_float2(x.z, x.w));
            uint2 pkk;
            pkk.x = pk(p0);
            pkk.y = pk(p1);
            *reinterpret_cast<uint2*>(&sA[r * SMSTRIDE + c4 * 4]) = pkk;

            float4 rv = *reinterpret_cast<const float4*>(&srv[ko * 64 + c4 * 4]);
            xqp[k] += x.x * x.x * rv.x + x.y * x.y * rv.y
                    + x.z * x.z * rv.z + x.w * x.w * rv.w;
        }
#pragma unroll
        for (int k = 0; k < 4; ++k) {
            int idx = tid + k * 256;
            int r = idx >> 3, c8 = idx & 7;
            uint4 vb = *reinterpret_cast<const uint4*>(&g_Mv[(size_t)r * DD + ko * 64 + c8 * 8]);
            *reinterpret_cast<uint4*>(&sB[r * SMSTRIDE + c8 * 8]) = vb;
        }
        __syncthreads();

#pragma unroll
        for (int ks = 0; ks < 4; ++ks) {
            int k0 = ks * 16 + tg * 2;
            uint32_t a0 = *reinterpret_cast<const uint32_t*>(&sA[(warp * 16 + g)     * SMSTRIDE + k0]);
            uint32_t a1 = *reinterpret_cast<const uint32_t*>(&sA[(warp * 16 + g + 8) * SMSTRIDE + k0]);
            uint32_t a2 = *reinterpret_cast<const uint32_t*>(&sA[(warp * 16 + g)     * SMSTRIDE + k0 + 8]);
            uint32_t a3 = *reinterpret_cast<const uint32_t*>(&sA[(warp * 16 + g + 8) * SMSTRIDE + k0 + 8]);
#pragma unroll
            for (int n = 0; n < 16; ++n) {
                uint32_t b0 = *reinterpret_cast<const uint32_t*>(&sB[(n * 8 + g) * SMSTRIDE + k0]);
                uint32_t b1 = *reinterpret_cast<const uint32_t*>(&sB[(n * 8 + g) * SMSTRIDE + k0 + 8]);
                mma_bf16(acc[n][0], acc[n][1], acc[n][2], acc[n][3], a0, a1, a2, a3, b0, b1);
            }
        }
        __syncthreads();
    }

    // xq reduce
#pragma unroll
    for (int k = 0; k < 8; ++k) {
        float s = xqp[k];
        s += __shfl_xor_sync(0xffffffffu, s, 1);
        s += __shfl_xor_sync(0xffffffffu, s, 2);
        s += __shfl_xor_sync(0xffffffffu, s, 4);
        s += __shfl_xor_sync(0xffffffffu, s, 8);
        if ((lane & 15) == 0) sXQ[(tid >> 4) + k * 16] = -0.5f * s;
    }
    __syncthreads();

    int r0l = warp * 16 + g;
    int r1l = r0l + 8;
    int r0 = mbase + r0l;
    float xq0 = sXQ[r0l], xq1 = sXQ[r1l];

    float mx0 = -1e30f, mx1 = -1e30f;
#pragma unroll
    for (int n = 0; n < 16; ++n) {
        int col = n * 8 + tg * 2;
        float cb0 = scb[col], cb1 = scb[col + 1];
        acc[n][0] += cb0; acc[n][1] += cb1;
        acc[n][2] += cb0; acc[n][3] += cb1;
        mx0 = fmaxf(mx0, fmaxf(acc[n][0], acc[n][1]));
        mx1 = fmaxf(mx1, fmaxf(acc[n][2], acc[n][3]));
    }
    mx0 = fmaxf(mx0, __shfl_xor_sync(0xffffffffu, mx0, 1));
    mx0 = fmaxf(mx0, __shfl_xor_sync(0xffffffffu, mx0, 2));
    mx1 = fmaxf(mx1, __shfl_xor_sync(0xffffffffu, mx1, 1));
    mx1 = fmaxf(mx1, __shfl_xor_sync(0xffffffffu, mx1, 2));

    // E fragment write, lane-major: [((l*32+btile)*16 + n)*32 + lane]
    int b = r0 & (BB - 1);
    int l = r0 >> 9;
    int btile = b >> 4;
    uint2* eout = &g_Efrag[((size_t)(l * 32 + btile) * 16) * 32 + lane];
#pragma unroll
    for (int n = 0; n < 16; ++n) {
        __nv_bfloat162 e01 = __floats2bfloat162_rn(fexp(acc[n][0] - mx0), fexp(acc[n][1] - mx0));
        __nv_bfloat162 e23 = __floats2bfloat162_rn(fexp(acc[n][2] - mx1), fexp(acc[n][3] - mx1));
        eout[n * 32] = make_uint2(pk(e01), pk(e23));
    }
    if (tg == 0) {
        g_dmaxT[(size_t)b * LL + l]       = mx0 + xq0;
        g_dmaxT[(size_t)(b + 8) * LL + l] = mx1 + xq1;
    }
}

// =====================================================================
// Kernel 3: forward recurrence — 4-warp n-split tensor-core version.
// 32 CTAs x 128 threads. Warp w owns output states n in [32w, 32w+32):
// 32 HMMA/step on its own SMSP tensor unit. B (A^T) frags hoisted to regs.
// p exchanged via double-buffered smem tile, 1 barrier/step.
// Dynamic smem arena (54.4 KB > 48 KB static cap).
// =====================================================================
#define ATSTRIDE 136   // bf16 elems per padded row (272 B)
#define PSTRIDE  136

// dynamic smem layout (byte offsets, all 16B-aligned)
#define OFF_AT    0                         // 128*136*2      = 34816
#define OFF_P0    34816                     // 16*136*2       = 4352
#define OFF_P1    (OFF_P0 + 4352)           //                = 39168
#define OFF_DMAX  (OFF_P1 + 4352)           // 128*16*4       = 8192  -> 43520
#define OFF_MK    (OFF_DMAX + 8192)         // 2048           -> 51712
#define OFF_SRN   (OFF_MK + 2048)           // 4*16*4 = 256   -> 53760
#define OFF_SSUM  (OFF_SRN + 256)           // 256            -> 54016
#define OFF_SM    (OFF_SSUM + 256)          // 64             -> 54272
#define RECUR_SMEM (OFF_SM + 64)            // 54336

__global__ __launch_bounds__(128) void recur_kernel(const float* __restrict__ masks) {
    extern __shared__ __align__(16) unsigned char dyn[];
    __nv_bfloat16* sAt = reinterpret_cast<__nv_bfloat16*>(dyn + OFF_AT);
    __nv_bfloat16* sp0 = reinterpret_cast<__nv_bfloat16*>(dyn + OFF_P0);
    __nv_bfloat16* sp1 = reinterpret_cast<__nv_bfloat16*>(dyn + OFF_P1);
    float* sdmax = reinterpret_cast<float*>(dyn + OFF_DMAX);
    unsigned char* smk = dyn + OFF_MK;
    float (*srn)[16]  = reinterpret_cast<float (*)[16]>(dyn + OFF_SRN);
    float (*ssum)[16] = reinterpret_cast<float (*)[16]>(dyn + OFF_SSUM);
    float* sM = reinterpret_cast<float*>(dyn + OFF_SM);

    int tid   = threadIdx.x;
    int lane  = tid & 31, w = tid >> 5;
    int btile = blockIdx.x;          // 0..31
    int g = lane >> 2, tg = lane & 3;

    // stage A^T with padding (all 128 threads)
    {
        const uint4* src = reinterpret_cast<const uint4*>(g_At);   // 2048 uint4
        for (int idx = tid; idx < 2048; idx += 128) {
            int j = idx >> 4, c = idx & 15;
            *reinterpret_cast<uint4*>(&sAt[j * ATSTRIDE + c * 8]) = src[idx];
        }
    }
    // stage dmax + masks for this CTA's 16 batches
    for (int idx = tid; idx < 2048; idx += 128) {
        int bi = idx >> 7, l = idx & 127;
        sdmax[l * 16 + bi] = g_dmaxT[(size_t)(btile * 16 + bi) * LL + l];
        smk[l * 16 + bi]   = (masks[l * BB + btile * 16 + bi] >= 0.5f) ? 1 : 0;
    }
    __syncthreads();

    // ---- hoist B fragments: warp w covers np in {2w, 2w+1} ----
    int q = lane >> 3, r = lane & 7;
    int rowb = ((q & 2) ? 8 : 0) + r;
    int kofs = (q & 1) ? 8 : 0;
    uint32_t bbase = smem_u32(&sAt[rowb * ATSTRIDE + kofs]);
    uint32_t bf[64];
#pragma unroll
    for (int kt = 0; kt < 8; ++kt)
#pragma unroll
        for (int npl = 0; npl < 2; ++npl) {
            int np = 2 * w + npl;
            ldmx4(bf[(kt * 2 + npl) * 4 + 0], bf[(kt * 2 + npl) * 4 + 1],
                  bf[(kt * 2 + npl) * 4 + 2], bf[(kt * 2 + npl) * 4 + 3],
                  bbase + np * (16 * ATSTRIDE * 2) + kt * 32);
        }

    // E pointer for this CTA / lane
    const uint2* __restrict__ Eb = g_Efrag + (size_t)btile * 512 + lane;  // + l*16384 + nt*32

    // ---- init: p = E[0]; store own slice into sp0 ----
    uint32_t pv01[4], pv23[4];   // p' slice, rows g / g+8, packed bf16x2
#pragma unroll
    for (int lt = 0; lt < 4; ++lt) {
        uint2 e = Eb[(4 * w + lt) * 32];
        pv01[lt] = e.x;
        pv23[lt] = e.y;
    }
#pragma unroll
    for (int lt = 0; lt < 4; ++lt) {
        int col = (4 * w + lt) * 8 + 2 * tg;
        *reinterpret_cast<uint32_t*>(&sp0[g * PSTRIDE + col])       = pv01[lt];
        *reinterpret_cast<uint32_t*>(&sp0[(g + 8) * PSTRIDE + col]) = pv23[lt];
    }
    float Mg = LOGPI_INIT + sdmax[g];
    float Mh = LOGPI_INIT + sdmax[g + 8];
    __syncthreads();

    // a-frag ldmatrix lane addresses
    int arow = (lane & 7) + ((lane & 8) ? 8 : 0);
    int akof = (lane & 16) ? 8 : 0;
    uint32_t abase[2];
    abase[0] = smem_u32(&sp0[arow * PSTRIDE + akof]);
    abase[1] = smem_u32(&sp1[arow * PSTRIDE + akof]);

    int buf = 0;
    for (int l = 1; l < LL; ++l) {
        // load full-k a-frags from the current p buffer
        uint32_t af[32];
#pragma unroll
        for (int kt = 0; kt < 8; ++kt)
            ldmx4(af[kt * 4 + 0], af[kt * 4 + 1], af[kt * 4 + 2], af[kt * 4 + 3],
                  abase[buf] + kt * 32);

        // prefetch E for own n-slice
        const uint2* Ep = Eb + (size_t)l * 16384;
        uint2 ef[4];
#pragma unroll
        for (int lt = 0; lt < 4; ++lt) ef[lt] = Ep[(4 * w + lt) * 32];

        float dm0 = sdmax[l * 16 + g];
        float dm1 = sdmax[l * 16 + g + 8];
        int mk0 = smk[l * 16 + g];
        int mk1 = smk[l * 16 + g + 8];

        float acc[4][4];
#pragma unroll
        for (int n = 0; n < 4; ++n)
#pragma unroll
            for (int k = 0; k < 4; ++k) acc[n][k] = 0.f;

        // 32 HMMA: 8 k-tiles x 2 n-pairs (own slice)
#pragma unroll
        for (int kt = 0; kt < 8; ++kt) {
            uint32_t a0 = af[kt * 4 + 0], a1 = af[kt * 4 + 1];
            uint32_t a2 = af[kt * 4 + 2], a3 = af[kt * 4 + 3];
#pragma unroll
            for (int npl = 0; npl < 2; ++npl) {
                const uint32_t* bb = &bf[(kt * 2 + npl) * 4];
                mma_bf16(acc[2 * npl][0], acc[2 * npl][1], acc[2 * npl][2], acc[2 * npl][3],
                         a0, a1, a2, a3, bb[0], bb[1]);
                mma_bf16(acc[2 * npl + 1][0], acc[2 * npl + 1][1], acc[2 * npl + 1][2], acc[2 * npl + 1][3],
                         a0, a1, a2, a3, bb[2], bb[3]);
            }
        }

        // epilogue: * E, mask blend (packed select)
#pragma unroll
        for (int lt = 0; lt < 4; ++lt) {
            float2 eg = __bfloat1622float2(upk(ef[lt].x));
            float2 eh = __bfloat1622float2(upk(ef[lt].y));
            uint32_t u01 = pk(__floats2bfloat162_rn(acc[lt][0] * eg.x, acc[lt][1] * eg.y));
            uint32_t u23 = pk(__floats2bfloat162_rn(acc[lt][2] * eh.x, acc[lt][3] * eh.y));
            if (!mk0) u01 = pv01[lt];
            if (!mk1) u23 = pv23[lt];
            pv01[lt] = u01;
            pv23[lt] = u23;
        }
        if (mk0) Mg += dm0;
        if (mk1) Mh += dm1;

        // periodic renorm (cross-warp max -> fold into M)
        if ((l & 7) == 0) {
            float mg = 1e-30f, mh = 1e-30f;
#pragma unroll
            for (int lt = 0; lt < 4; ++lt) {
                float2 v01 = __bfloat1622float2(upk(pv01[lt]));
                float2 v23 = __bfloat1622float2(upk(pv23[lt]));
                mg = fmaxf(mg, fmaxf(v01.x, v01.y));
                mh = fmaxf(mh, fmaxf(v23.x, v23.y));
            }
            mg = fmaxf(mg, __shfl_xor_sync(0xffffffffu, mg, 1));
            mg = fmaxf(mg, __shfl_xor_sync(0xffffffffu, mg, 2));
            mh = fmaxf(mh, __shfl_xor_sync(0xffffffffu, mh, 1));
            mh = fmaxf(mh, __shfl_xor_sync(0xffffffffu, mh, 2));
            if (tg == 0) { srn[w][g] = mg; srn[w][g + 8] = mh; }
            __syncthreads();
            mg = fmaxf(fmaxf(srn[0][g], srn[1][g]), fmaxf(srn[2][g], srn[3][g]));
            mh = fmaxf(fmaxf(srn[0][g + 8], srn[1][g + 8]), fmaxf(srn[2][g + 8], srn[3][g + 8]));
            float rg = 1.f / mg, rh = 1.f / mh;
#pragma unroll
            for (int lt = 0; lt < 4; ++lt) {
                float2 v01 = __bfloat1622float2(upk(pv01[lt]));
                float2 v23 = __bfloat1622float2(upk(pv23[lt]));
                pv01[lt] = pk(__floats2bfloat162_rn(v01.x * rg, v01.y * rg));
                pv23[lt] = pk(__floats2bfloat162_rn(v23.x * rh, v23.y * rh));
            }
            Mg += __logf(mg);
            Mh += __logf(mh);
        }

        // store own slice to the other buffer, then one barrier
        int nbuf = buf ^ 1;
        {
            __nv_bfloat16* base = nbuf ? sp1 : sp0;
#pragma unroll
            for (int lt = 0; lt < 4; ++lt) {
                int col = (4 * w + lt) * 8 + 2 * tg;
                *reinterpret_cast<uint32_t*>(&base[g * PSTRIDE + col])       = pv01[lt];
                *reinterpret_cast<uint32_t*>(&base[(g + 8) * PSTRIDE + col]) = pv23[lt];
            }
        }
        __syncthreads();
        buf = nbuf;
    }

    // objective per batch: M + log(sum_j p_j); combine across warps
    float Sg = 0.f, Sh = 0.f;
#pragma unroll
    for (int lt = 0; lt < 4; ++lt) {
        float2 v01 = __bfloat1622float2(upk(pv01[lt]));
        float2 v23 = __bfloat1622float2(upk(pv23[lt]));
        Sg += v01.x + v01.y;
        Sh += v23.x + v23.y;
    }
    Sg += __shfl_xor_sync(0xffffffffu, Sg, 1);
    Sg += __shfl_xor_sync(0xffffffffu, Sg, 2);
    Sh += __shfl_xor_sync(0xffffffffu, Sh, 1);
    Sh += __shfl_xor_sync(0xffffffffu, Sh, 2);
    if (tg == 0) {
        ssum[w][g] = Sg;
        ssum[w][g + 8] = Sh;
        if (w == 0) { sM[g] = Mg; sM[g + 8] = Mh; }
    }
    __syncthreads();
    if (tid < 16) {
        float S = ssum[0][tid] + ssum[1][tid] + ssum[2][tid] + ssum[3][tid];
        S = fmaxf(S, 1e-37f);
        g_perb[btile * 16 + tid] = sM[tid] + __logf(S);
    }
}

// =====================================================================
// Kernel 4: deterministic final reduction over 512 batch rows
// =====================================================================
__global__ void finalize_kernel(float* __restrict__ out, int out_size) {
    __shared__ float s[256];
    int t = threadIdx.x;
    s[t] = g_perb[t] + g_perb[t + 256];
    __syncthreads();
    for (int off = 128; off > 0; off >>= 1) {
        if (t < off) s[t] += s[t + off];
        __syncthreads();
    }
    for (int i = t; i < out_size; i += 256)
        if (i != 0) out[i] = 0.f;   // jacobian_loss = 0
    if (t == 0) out[0] = s[0];
}

// =====================================================================
extern "C" void kernel_launch(void* const* d_in, const int* in_sizes, int n_in,
                              void* d_out, int out_size) {
    const float* sents   = (const float*)d_in[0];
    const float* masks   = (const float*)d_in[1];
    const float* tparams = (const float*)d_in[2];
    const float* means   = (const float*)d_in[3];
    const float* var     = (const float*)d_in[4];
    float* out = (float*)d_out;

    cudaFuncSetAttribute(recur_kernel, cudaFuncAttributeMaxDynamicSharedMemorySize, RECUR_SMEM);

    prep_kernel<<<1, 512>>>(tparams, means, var);
    density_kernel<<<LB / 128, 256>>>(sents);
    recur_kernel<<<32, 128, RECUR_SMEM>>>(masks);
    finalize_kernel<<<1, 256>>>(out, out_size);
}

// round 8
// speedup vs baseline: 1.2293x; 1.0098x over previous
#include <cuda_runtime.h>
#include <cuda_bf16.h>
#include <cstdint>
#include <math.h>

// Problem constants
#define LL 128
#define BB 512
#define DD 512
#define SS 128
#define LB (LL * BB)   // 65536

// -------- device scratch --------
__device__ __align__(16) float          g_colbias[SS];
__device__ __align__(16) float          g_rvar[DD];
__device__ __align__(16) __nv_bfloat16  g_Mv[SS * DD];          // mu/var bf16, [s][d]
__device__ __align__(16) __nv_bfloat16  g_At[SS * SS];          // A transposed: At[j][i] = A[i][j], bf16
// E in mma-fragment layout, lane-major: [((l*32 + btile)*16 + n)*32 + lane]
__device__ __align__(16) uint2          g_Efrag[(size_t)LL * 32 * 16 * 32]; // 16 MB
__device__ __align__(16) float          g_dmaxT[BB * LL];       // dmax transposed: [b][l]
__device__ __align__(16) float          g_perb[BB];

#define LOG2PI 1.8378770664093453f
#define LOGPI_INIT (-4.852030263919617f)   // -log(128)

// ---- fast exp on the FMA pipe (x <= 0 expected; flushes below -80) ----
__device__ __forceinline__ float fexp(float x) {
    float t = fmaf(x, 1.4426950408889634f, 12582912.0f);
    int   ni = __float_as_int(t) - 0x4B400000;
    float n  = t - 12582912.0f;
    float f  = fmaf(x, 1.4426950408889634f, -n);
    float r  = 0.0013333558f;
    r = fmaf(r, f, 0.0096181291f);
    r = fmaf(r, f, 0.0555041087f);
    r = fmaf(r, f, 0.2402264689f);
    r = fmaf(r, f, 0.6931471806f);
    r = fmaf(r, f, 1.0f);
    float res = __int_as_float(__float_as_int(r) + (ni << 23));
    return (x > -80.0f) ? res : 0.0f;
}

__device__ __forceinline__ uint32_t pk(__nv_bfloat162 v) { return *reinterpret_cast<uint32_t*>(&v); }
__device__ __forceinline__ __nv_bfloat162 upk(uint32_t v) { return *reinterpret_cast<__nv_bfloat162*>(&v); }
__device__ __forceinline__ uint32_t smem_u32(const void* p) {
    return (uint32_t)__cvta_generic_to_shared(p);
}

__device__ __forceinline__ void mma_bf16(float& c0, float& c1, float& c2, float& c3,
                                         uint32_t a0, uint32_t a1, uint32_t a2, uint32_t a3,
                                         uint32_t b0, uint32_t b1) {
    asm volatile(
        "mma.sync.aligned.m16n8k16.row.col.f32.bf16.bf16.f32 "
        "{%0,%1,%2,%3}, {%4,%5,%6,%7}, {%8,%9}, {%0,%1,%2,%3};\n"
        : "+f"(c0), "+f"(c1), "+f"(c2), "+f"(c3)
        : "r"(a0), "r"(a1), "r"(a2), "r"(a3), "r"(b0), "r"(b1));
}

__device__ __forceinline__ void ldmx4(uint32_t& r0, uint32_t& r1, uint32_t& r2, uint32_t& r3,
                                      uint32_t addr) {
    asm volatile("ldmatrix.sync.aligned.m8n8.x4.shared.b16 {%0,%1,%2,%3}, [%4];"
                 : "=r"(r0), "=r"(r1), "=r"(r2), "=r"(r3) : "r"(addr));
}

// =====================================================================
// Kernel 1: preprocessing (1 block, 512 threads)
// =====================================================================
__global__ void prep_kernel(const float* __restrict__ tparams,
                            const float* __restrict__ means,
                            const float* __restrict__ var) {
    __shared__ float sred[512];
    int t = threadIdx.x;

    float v = var[t];
    g_rvar[t] = 1.0f / v;
    sred[t] = logf(v);
    __syncthreads();
    for (int off = 256; off > 0; off >>= 1) {
        if (t < off) sred[t] += sred[t + off];
        __syncthreads();
    }
    float slv = sred[0];
    float c = -256.0f * LOG2PI - 0.5f * slv;

    int q   = t & 3;      // 0..3
    int grp = t >> 2;     // 0..127  (row i)

    // col bias
    {
        float mq = 0.f;
        for (int d = q; d < DD; d += 4) {
            float m = means[grp * DD + d];
            mq += m * m * g_rvar[d];
        }
        mq += __shfl_xor_sync(0xffffffffu, mq, 1);
        mq += __shfl_xor_sync(0xffffffffu, mq, 2);
        if (q == 0) g_colbias[grp] = c - 0.5f * mq;
    }

    // At[j][i] = exp(tparams[i][j] - lse_j'(tparams[i][:]))
    {
        float mx = -1e30f;
        for (int jj = q; jj < SS; jj += 4) mx = fmaxf(mx, tparams[grp * SS + jj]);
        mx = fmaxf(mx, __shfl_xor_sync(0xffffffffu, mx, 1));
        mx = fmaxf(mx, __shfl_xor_sync(0xffffffffu, mx, 2));
        float se = 0.f;
        for (int jj = q; jj < SS; jj += 4) se += __expf(tparams[grp * SS + jj] - mx);
        se += __shfl_xor_sync(0xffffffffu, se, 1);
        se += __shfl_xor_sync(0xffffffffu, se, 2);
        float lse = mx + __logf(se);
        for (int jj = q; jj < SS; jj += 4)
            g_At[jj * SS + grp] = __float2bfloat16(__expf(tparams[grp * SS + jj] - lse));
    }

    // Mv = mu / var in bf16
    for (int idx = t; idx < SS * DD; idx += 512) {
        int d = idx & (DD - 1);
        g_Mv[idx] = __float2bfloat16(means[idx] * g_rvar[d]);
    }
}

// =====================================================================
// Kernel 2: fused density GEMM -> E (fragment layout, bf16) + dmaxT
// =====================================================================
#define SMSTRIDE 72

__global__ __launch_bounds__(256) void density_kernel(const float* __restrict__ sents) {
    __shared__ __align__(16) __nv_bfloat16 sA[128 * SMSTRIDE];
    __shared__ __align__(16) __nv_bfloat16 sB[128 * SMSTRIDE];
    __shared__ __align__(16) float srv[DD];
    __shared__ float sXQ[128];
    __shared__ float scb[128];

    int tid  = threadIdx.x;
    int warp = tid >> 5, lane = tid & 31;
    int g = lane >> 2, tg = lane & 3;
    int mbase = blockIdx.x * 128;

    for (int i = tid; i < DD; i += 256) srv[i] = g_rvar[i];
    if (tid < 128) scb[tid] = g_colbias[tid];

    float acc[16][4];
#pragma unroll
    for (int n = 0; n < 16; ++n)
#pragma unroll
        for (int k = 0; k < 4; ++k) acc[n][k] = 0.f;

    float xqp[8];
#pragma unroll
    for (int k = 0; k < 8; ++k) xqp[k] = 0.f;

    __syncthreads();

    for (int ko = 0; ko < 8; ++ko) {
#pragma unroll
        for (int k = 0; k < 8; ++k) {
            int idx = tid + k * 256;
            int r = idx >> 4, c4 = idx & 15;
            float4 x = *reinterpret_cast<const float4*>(
                &sents[(size_t)(mbase + r) * DD + ko * 64 + c4 * 4]);
            __nv_bfloat162 p0 = __float22bfloat162_rn(make_float2(x.x, x.y));
            __nv_bfloat162 p1 = __float22bfloat162_rn(make_float2(x.z, x.w));
            uint2 pkk;
            pkk.x = pk(p0);
            pkk.y = pk(p1);
            *reinterpret_cast<uint2*>(&sA[r * SMSTRIDE + c4 * 4]) = pkk;

            float4 rv = *reinterpret_cast<const float4*>(&srv[ko * 64 + c4 * 4]);
            xqp[k] += x.x * x.x * rv.x + x.y * x.y * rv.y
                    + x.z * x.z * rv.z + x.w * x.w * rv.w;
        }
#pragma unroll
        for (int k = 0; k < 4; ++k) {
            int idx = tid + k * 256;
            int r = idx >> 3, c8 = idx & 7;
            uint4 vb = *reinterpret_cast<const uint4*>(&g_Mv[(size_t)r * DD + ko * 64 + c8 * 8]);
            *reinterpret_cast<uint4*>(&sB[r * SMSTRIDE + c8 * 8]) = vb;
        }
        __syncthreads();

#pragma unroll
        for (int ks = 0; ks < 4; ++ks) {
            int k0 = ks * 16 + tg * 2;
            uint32_t a0 = *reinterpret_cast<const uint32_t*>(&sA[(warp * 16 + g)     * SMSTRIDE + k0]);
            uint32_t a1 = *reinterpret_cast<const uint32_t*>(&sA[(warp * 16 + g + 8) * SMSTRIDE + k0]);
            uint32_t a2 = *reinterpret_cast<const uint32_t*>(&sA[(warp * 16 + g)     * SMSTRIDE + k0 + 8]);
            uint32_t a3 = *reinterpret_cast<const uint32_t*>(&sA[(warp * 16 + g + 8) * SMSTRIDE + k0 + 8]);
#pragma unroll
            for (int n = 0; n < 16; ++n) {
                uint32_t b0 = *reinterpret_cast<const uint32_t*>(&sB[(n * 8 + g) * SMSTRIDE + k0]);
                uint32_t b1 = *reinterpret_cast<const uint32_t*>(&sB[(n * 8 + g) * SMSTRIDE + k0 + 8]);
                mma_bf16(acc[n][0], acc[n][1], acc[n][2], acc[n][3], a0, a1, a2, a3, b0, b1);
            }
        }
        __syncthreads();
    }

    // xq reduce
#pragma unroll
    for (int k = 0; k < 8; ++k) {
        float s = xqp[k];
        s += __shfl_xor_sync(0xffffffffu, s, 1);
        s += __shfl_xor_sync(0xffffffffu, s, 2);
        s += __shfl_xor_sync(0xffffffffu, s, 4);
        s += __shfl_xor_sync(0xffffffffu, s, 8);
        if ((lane & 15) == 0) sXQ[(tid >> 4) + k * 16] = -0.5f * s;
    }
    __syncthreads();

    int r0l = warp * 16 + g;
    int r1l = r0l + 8;
    int r0 = mbase + r0l;
    float xq0 = sXQ[r0l], xq1 = sXQ[r1l];

    float mx0 = -1e30f, mx1 = -1e30f;
#pragma unroll
    for (int n = 0; n < 16; ++n) {
        int col = n * 8 + tg * 2;
        float cb0 = scb[col], cb1 = scb[col + 1];
        acc[n][0] += cb0; acc[n][1] += cb1;
        acc[n][2] += cb0; acc[n][3] += cb1;
        mx0 = fmaxf(mx0, fmaxf(acc[n][0], acc[n][1]));
        mx1 = fmaxf(mx1, fmaxf(acc[n][2], acc[n][3]));
    }
    mx0 = fmaxf(mx0, __shfl_xor_sync(0xffffffffu, mx0, 1));
    mx0 = fmaxf(mx0, __shfl_xor_sync(0xffffffffu, mx0, 2));
    mx1 = fmaxf(mx1, __shfl_xor_sync(0xffffffffu, mx1, 1));
    mx1 = fmaxf(mx1, __shfl_xor_sync(0xffffffffu, mx1, 2));

    // E fragment write, lane-major: [((l*32+btile)*16 + n)*32 + lane]
    int b = r0 & (BB - 1);
    int l = r0 >> 9;
    int btile = b >> 4;
    uint2* eout = &g_Efrag[((size_t)(l * 32 + btile) * 16) * 32 + lane];
#pragma unroll
    for (int n = 0; n < 16; ++n) {
        __nv_bfloat162 e01 = __floats2bfloat162_rn(fexp(acc[n][0] - mx0), fexp(acc[n][1] - mx0));
        __nv_bfloat162 e23 = __floats2bfloat162_rn(fexp(acc[n][2] - mx1), fexp(acc[n][3] - mx1));
        eout[n * 32] = make_uint2(pk(e01), pk(e23));
    }
    if (tg == 0) {
        g_dmaxT[(size_t)b * LL + l]       = mx0 + xq0;
        g_dmaxT[(size_t)(b + 8) * LL + l] = mx1 + xq1;
    }
}

// =====================================================================
// Kernel 3: forward recurrence — 8-warp n-split tensor-core version.
// 32 CTAs x 256 threads. Warp w owns output states n in [16w, 16w+16):
// 16 HMMA/step on its own SMSP tensor unit (2 warps/SMSP overlap issue).
// B (A^T) frags hoisted to regs. p via double-buffered smem, 1 barrier/step.
// =====================================================================
#define ATSTRIDE 136   // bf16 elems per padded row (272 B)
#define PSTRIDE  136

// dynamic smem layout (byte offsets, all 16B-aligned)
#define OFF_AT    0                         // 128*136*2      = 34816
#define OFF_P0    34816                     // 16*136*2       = 4352
#define OFF_P1    (OFF_P0 + 4352)           //                = 39168
#define OFF_DMAX  (OFF_P1 + 4352)           // 128*16*4       = 8192  -> 43520
#define OFF_MK    (OFF_DMAX + 8192)         // 2048           -> 51712
#define OFF_SRN   (OFF_MK + 2048)           // 8*16*4 = 512   -> 53760
#define OFF_SSUM  (OFF_SRN + 512)           // 512            -> 54272
#define OFF_SM    (OFF_SSUM + 512)          // 64             -> 54784
#define RECUR_SMEM (OFF_SM + 64)            // 54848

__global__ __launch_bounds__(256) void recur_kernel(const float* __restrict__ masks) {
    extern __shared__ __align__(16) unsigned char dyn[];
    __nv_bfloat16* sAt = reinterpret_cast<__nv_bfloat16*>(dyn + OFF_AT);
    __nv_bfloat16* sp0 = reinterpret_cast<__nv_bfloat16*>(dyn + OFF_P0);
    __nv_bfloat16* sp1 = reinterpret_cast<__nv_bfloat16*>(dyn + OFF_P1);
    float* sdmax = reinterpret_cast<float*>(dyn + OFF_DMAX);
    unsigned char* smk = dyn + OFF_MK;
    float (*srn)[16]  = reinterpret_cast<float (*)[16]>(dyn + OFF_SRN);
    float (*ssum)[16] = reinterpret_cast<float (*)[16]>(dyn + OFF_SSUM);
    float* sM = reinterpret_cast<float*>(dyn + OFF_SM);

    int tid   = threadIdx.x;
    int lane  = tid & 31, w = tid >> 5;     // w in [0,8)
    int btile = blockIdx.x;                  // 0..31
    int g = lane >> 2, tg = lane & 3;

    // stage A^T with padding (all 256 threads)
    {
        const uint4* src = reinterpret_cast<const uint4*>(g_At);   // 2048 uint4
        for (int idx = tid; idx < 2048; idx += 256) {
            int j = idx >> 4, c = idx & 15;
            *reinterpret_cast<uint4*>(&sAt[j * ATSTRIDE + c * 8]) = src[idx];
        }
    }
    // stage dmax + masks for this CTA's 16 batches
    for (int idx = tid; idx < 2048; idx += 256) {
        int bi = idx >> 7, l = idx & 127;
        sdmax[l * 16 + bi] = g_dmaxT[(size_t)(btile * 16 + bi) * LL + l];
        smk[l * 16 + bi]   = (masks[l * BB + btile * 16 + bi] >= 0.5f) ? 1 : 0;
    }
    __syncthreads();

    // ---- hoist B fragments: warp w covers n-pair group np = w ----
    int q = lane >> 3, r = lane & 7;
    int rowb = ((q & 2) ? 8 : 0) + r;
    int kofs = (q & 1) ? 8 : 0;
    uint32_t bbase = smem_u32(&sAt[rowb * ATSTRIDE + kofs]);
    uint32_t bf[32];
#pragma unroll
    for (int kt = 0; kt < 8; ++kt) {
        ldmx4(bf[kt * 4 + 0], bf[kt * 4 + 1], bf[kt * 4 + 2], bf[kt * 4 + 3],
              bbase + w * (16 * ATSTRIDE * 2) + kt * 32);
    }

    // E pointer for this CTA / lane
    const uint2* __restrict__ Eb = g_Efrag + (size_t)btile * 512 + lane;  // + l*16384 + nt*32

    // ---- init: p = E[0]; store own slice into sp0 ----
    uint32_t pv01[2], pv23[2];   // p' slice (nt = 2w+lt), rows g / g+8, packed bf16x2
#pragma unroll
    for (int lt = 0; lt < 2; ++lt) {
        uint2 e = Eb[(2 * w + lt) * 32];
        pv01[lt] = e.x;
        pv23[lt] = e.y;
    }
#pragma unroll
    for (int lt = 0; lt < 2; ++lt) {
        int col = (2 * w + lt) * 8 + 2 * tg;
        *reinterpret_cast<uint32_t*>(&sp0[g * PSTRIDE + col])       = pv01[lt];
        *reinterpret_cast<uint32_t*>(&sp0[(g + 8) * PSTRIDE + col]) = pv23[lt];
    }
    float Mg = LOGPI_INIT + sdmax[g];
    float Mh = LOGPI_INIT + sdmax[g + 8];
    __syncthreads();

    // a-frag ldmatrix lane addresses
    int arow = (lane & 7) + ((lane & 8) ? 8 : 0);
    int akof = (lane & 16) ? 8 : 0;
    uint32_t abase[2];
    abase[0] = smem_u32(&sp0[arow * PSTRIDE + akof]);
    abase[1] = smem_u32(&sp1[arow * PSTRIDE + akof]);

    int buf = 0;
    for (int l = 1; l < LL; ++l) {
        // load full-k a-frags from the current p buffer
        uint32_t af[32];
#pragma unroll
        for (int kt = 0; kt < 8; ++kt)
            ldmx4(af[kt * 4 + 0], af[kt * 4 + 1], af[kt * 4 + 2], af[kt * 4 + 3],
                  abase[buf] + kt * 32);

        // prefetch E for own n-slice
        const uint2* Ep = Eb + (size_t)l * 16384;
        uint2 ef[2];
#pragma unroll
        for (int lt = 0; lt < 2; ++lt) ef[lt] = Ep[(2 * w + lt) * 32];

        float dm0 = sdmax[l * 16 + g];
        float dm1 = sdmax[l * 16 + g + 8];
        int mk0 = smk[l * 16 + g];
        int mk1 = smk[l * 16 + g + 8];

        float acc[2][4];
#pragma unroll
        for (int n = 0; n < 2; ++n)
#pragma unroll
            for (int k = 0; k < 4; ++k) acc[n][k] = 0.f;

        // 16 HMMA: 8 k-tiles x 1 n-pair (own slice)
#pragma unroll
        for (int kt = 0; kt < 8; ++kt) {
            uint32_t a0 = af[kt * 4 + 0], a1 = af[kt * 4 + 1];
            uint32_t a2 = af[kt * 4 + 2], a3 = af[kt * 4 + 3];
            const uint32_t* bb = &bf[kt * 4];
            mma_bf16(acc[0][0], acc[0][1], acc[0][2], acc[0][3],
                     a0, a1, a2, a3, bb[0], bb[1]);
            mma_bf16(acc[1][0], acc[1][1], acc[1][2], acc[1][3],
                     a0, a1, a2, a3, bb[2], bb[3]);
        }

        // epilogue: * E, mask blend (packed select)
#pragma unroll
        for (int lt = 0; lt < 2; ++lt) {
            float2 eg = __bfloat1622float2(upk(ef[lt].x));
            float2 eh = __bfloat1622float2(upk(ef[lt].y));
            uint32_t u01 = pk(__floats2bfloat162_rn(acc[lt][0] * eg.x, acc[lt][1] * eg.y));
            uint32_t u23 = pk(__floats2bfloat162_rn(acc[lt][2] * eh.x, acc[lt][3] * eh.y));
            if (!mk0) u01 = pv01[lt];
            if (!mk1) u23 = pv23[lt];
            pv01[lt] = u01;
            pv23[lt] = u23;
        }
        if (mk0) Mg += dm0;
        if (mk1) Mh += dm1;

        // periodic renorm (cross-warp max -> fold into M)
        if ((l & 7) == 0) {
            float mg = 1e-30f, mh = 1e-30f;
#pragma unroll
            for (int lt = 0; lt < 2; ++lt) {
                float2 v01 = __bfloat1622float2(upk(pv01[lt]));
                float2 v23 = __bfloat1622float2(upk(pv23[lt]));
                mg = fmaxf(mg, fmaxf(v01.x, v01.y));
                mh = fmaxf(mh, fmaxf(v23.x, v23.y));
            }
            mg = fmaxf(mg, __shfl_xor_sync(0xffffffffu, mg, 1));
            mg = fmaxf(mg, __shfl_xor_sync(0xffffffffu, mg, 2));
            mh = fmaxf(mh, __shfl_xor_sync(0xffffffffu, mh, 1));
            mh = fmaxf(mh, __shfl_xor_sync(0xffffffffu, mh, 2));
            if (tg == 0) { srn[w][g] = mg; srn[w][g + 8] = mh; }
            __syncthreads();
#pragma unroll
            for (int ww = 0; ww < 8; ++ww) {
                mg = fmaxf(mg, srn[ww][g]);
                mh = fmaxf(mh, srn[ww][g + 8]);
            }
            float rg = 1.f / mg, rh = 1.f / mh;
#pragma unroll
            for (int lt = 0; lt < 2; ++lt) {
                float2 v01 = __bfloat1622float2(upk(pv01[lt]));
                float2 v23 = __bfloat1622float2(upk(pv23[lt]));
                pv01[lt] = pk(__floats2bfloat162_rn(v01.x * rg, v01.y * rg));
                pv23[lt] = pk(__floats2bfloat162_rn(v23.x * rh, v23.y * rh));
            }
            Mg += __logf(mg);
            Mh += __logf(mh);
        }

        // store own slice to the other buffer, then one barrier
        int nbuf = buf ^ 1;
        {
            __nv_bfloat16* base = nbuf ? sp1 : sp0;
#pragma unroll
            for (int lt = 0; lt < 2; ++lt) {
                int col = (2 * w + lt) * 8 + 2 * tg;
                *reinterpret_cast<uint32_t*>(&base[g * PSTRIDE + col])       = pv01[lt];
                *reinterpret_cast<uint32_t*>(&base[(g + 8) * PSTRIDE + col]) = pv23[lt];
            }
        }
        __syncthreads();
        buf = nbuf;
    }

    // objective per batch: M + log(sum_j p_j); combine across warps
    float Sg = 0.f, Sh = 0.f;
#pragma unroll
    for (int lt = 0; lt < 2; ++lt) {
        float2 v01 = __bfloat1622float2(upk(pv01[lt]));
        float2 v23 = __bfloat1622float2(upk(pv23[lt]));
        Sg += v01.x + v01.y;
        Sh += v23.x + v23.y;
    }
    Sg += __shfl_xor_sync(0xffffffffu, Sg, 1);
    Sg += __shfl_xor_sync(0xffffffffu, Sg, 2);
    Sh += __shfl_xor_sync(0xffffffffu, Sh, 1);
    Sh += __shfl_xor_sync(0xffffffffu, Sh, 2);
    if (tg == 0) {
        ssum[w][g] = Sg;
        ssum[w][g + 8] = Sh;
        if (w == 0) { sM[g] = Mg; sM[g + 8] = Mh; }
    }
    __syncthreads();
    if (tid < 16) {
        float S = 0.f;
#pragma unroll
        for (int ww = 0; ww < 8; ++ww) S += ssum[ww][tid];
        S = fmaxf(S, 1e-37f);
        g_perb[btile * 16 + tid] = sM[tid] + __logf(S);
    }
}

// =====================================================================
// Kernel 4: deterministic final reduction over 512 batch rows
// =====================================================================
__global__ void finalize_kernel(float* __restrict__ out, int out_size) {
    __shared__ float s[256];
    int t = threadIdx.x;
    s[t] = g_perb[t] + g_perb[t + 256];
    __syncthreads();
    for (int off = 128; off > 0; off >>= 1) {
        if (t < off) s[t] += s[t + off];
        __syncthreads();
    }
    for (int i = t; i < out_size; i += 256)
        if (i != 0) out[i] = 0.f;   // jacobian_loss = 0
    if (t == 0) out[0] = s[0];
}

// =====================================================================
extern "C" void kernel_launch(void* const* d_in, const int* in_sizes, int n_in,
                              void* d_out, int out_size) {
    const float* sents   = (const float*)d_in[0];
    const float* masks   = (const float*)d_in[1];
    const float* tparams = (const float*)d_in[2];
    const float* means   = (const float*)d_in[3];
    const float* var     = (const float*)d_in[4];
    float* out = (float*)d_out;

    cudaFuncSetAttribute(recur_kernel, cudaFuncAttributeMaxDynamicSharedMemorySize, RECUR_SMEM);

    prep_kernel<<<1, 512>>>(tparams, means, var);
    density_kernel<<<LB / 128, 256>>>(sents);
    recur_kernel<<<32, 256, RECUR_SMEM>>>(masks);
    finalize_kernel<<<1, 256>>>(out, out_size);
}

// round 9
// speedup vs baseline: 2.1696x; 1.7649x over previous
#include <cuda_runtime.h>
#include <cuda_bf16.h>
#include <cstdint>
#include <math.h>

// Problem constants
#define LL 128
#define BB 512
#define DD 512
#define SS 128
#define LB (LL * BB)   // 65536

// -------- device scratch --------
__device__ __align__(16) float          g_colbias[SS];
__device__ __align__(16) float          g_rvar[DD];
__device__ __align__(16) float          g_xq[LB];               // -0.5*sum x^2/var
__device__ __align__(16) __nv_bfloat16  g_Xs[(size_t)LB * DD];  // X in bf16 (64 MB)
__device__ __align__(16) __nv_bfloat16  g_Mv[SS * DD];          // mu/var bf16, [s][d]
__device__ __align__(16) __nv_bfloat16  g_At[SS * SS];          // A^T bf16
// E in mma-fragment layout, lane-major: [((l*32 + btile)*16 + n)*32 + lane]
__device__ __align__(16) uint2          g_Efrag[(size_t)LL * 32 * 16 * 32]; // 16 MB
__device__ __align__(16) float          g_dmaxT[BB * LL];       // dmax transposed: [b][l]
__device__ __align__(16) float          g_perb[BB];

#define LOG2PI 1.8378770664093453f
#define LOGPI_INIT (-4.852030263919617f)   // -log(128)

// ---- fast exp on the FMA pipe (x <= 0 expected; flushes below -80) ----
__device__ __forceinline__ float fexp(float x) {
    float t = fmaf(x, 1.4426950408889634f, 12582912.0f);
    int   ni = __float_as_int(t) - 0x4B400000;
    float n  = t - 12582912.0f;
    float f  = fmaf(x, 1.4426950408889634f, -n);
    float r  = 0.0013333558f;
    r = fmaf(r, f, 0.0096181291f);
    r = fmaf(r, f, 0.0555041087f);
    r = fmaf(r, f, 0.2402264689f);
    r = fmaf(r, f, 0.6931471806f);
    r = fmaf(r, f, 1.0f);
    float res = __int_as_float(__float_as_int(r) + (ni << 23));
    return (x > -80.0f) ? res : 0.0f;
}

__device__ __forceinline__ uint32_t pk(__nv_bfloat162 v) { return *reinterpret_cast<uint32_t*>(&v); }
__device__ __forceinline__ __nv_bfloat162 upk(uint32_t v) { return *reinterpret_cast<__nv_bfloat162*>(&v); }
__device__ __forceinline__ uint32_t smem_u32(const void* p) {
    return (uint32_t)__cvta_generic_to_shared(p);
}

__device__ __forceinline__ void mma_bf16(float& c0, float& c1, float& c2, float& c3,
                                         uint32_t a0, uint32_t a1, uint32_t a2, uint32_t a3,
                                         uint32_t b0, uint32_t b1) {
    asm volatile(
        "mma.sync.aligned.m16n8k16.row.col.f32.bf16.bf16.f32 "
        "{%0,%1,%2,%3}, {%4,%5,%6,%7}, {%8,%9}, {%0,%1,%2,%3};\n"
        : "+f"(c0), "+f"(c1), "+f"(c2), "+f"(c3)
        : "r"(a0), "r"(a1), "r"(a2), "r"(a3), "r"(b0), "r"(b1));
}

__device__ __forceinline__ void ldmx4(uint32_t& r0, uint32_t& r1, uint32_t& r2, uint32_t& r3,
                                      uint32_t addr) {
    asm volatile("ldmatrix.sync.aligned.m8n8.x4.shared.b16 {%0,%1,%2,%3}, [%4];"
                 : "=r"(r0), "=r"(r1), "=r"(r2), "=r"(r3) : "r"(addr));
}

// =====================================================================
// Kernel 1: preprocessing (1 block, 512 threads)
// =====================================================================
__global__ void prep_kernel(const float* __restrict__ tparams,
                            const float* __restrict__ means,
                            const float* __restrict__ var) {
    __shared__ float sred[512];
    int t = threadIdx.x;

    float v = var[t];
    g_rvar[t] = 1.0f / v;
    sred[t] = logf(v);
    __syncthreads();
    for (int off = 256; off > 0; off >>= 1) {
        if (t < off) sred[t] += sred[t + off];
        __syncthreads();
    }
    float slv = sred[0];
    float c = -256.0f * LOG2PI - 0.5f * slv;

    int q   = t & 3;      // 0..3
    int grp = t >> 2;     // 0..127  (row i)

    // col bias
    {
        float mq = 0.f;
        for (int d = q; d < DD; d += 4) {
            float m = means[grp * DD + d];
            mq += m * m * g_rvar[d];
        }
        mq += __shfl_xor_sync(0xffffffffu, mq, 1);
        mq += __shfl_xor_sync(0xffffffffu, mq, 2);
        if (q == 0) g_colbias[grp] = c - 0.5f * mq;
    }

    // At[j][i] = exp(tparams[i][j] - lse_j'(tparams[i][:]))
    {
        float mx = -1e30f;
        for (int jj = q; jj < SS; jj += 4) mx = fmaxf(mx, tparams[grp * SS + jj]);
        mx = fmaxf(mx, __shfl_xor_sync(0xffffffffu, mx, 1));
        mx = fmaxf(mx, __shfl_xor_sync(0xffffffffu, mx, 2));
        float se = 0.f;
        for (int jj = q; jj < SS; jj += 4) se += __expf(tparams[grp * SS + jj] - mx);
        se += __shfl_xor_sync(0xffffffffu, se, 1);
        se += __shfl_xor_sync(0xffffffffu, se, 2);
        float lse = mx + __logf(se);
        for (int jj = q; jj < SS; jj += 4)
            g_At[jj * SS + grp] = __float2bfloat16(__expf(tparams[grp * SS + jj] - lse));
    }

    // Mv = mu / var in bf16
    for (int idx = t; idx < SS * DD; idx += 512) {
        int d = idx & (DD - 1);
        g_Mv[idx] = __float2bfloat16(means[idx] * g_rvar[d]);
    }
}

// =====================================================================
// Kernel 2: per-row -0.5*sum(x^2/var) + bf16 cast of X (DRAM-bound)
// grid = LB/8 blocks, 256 threads (8 warps, 1 row per warp)  [proven in R1]
// =====================================================================
__global__ __launch_bounds__(256) void xqcast_kernel(const float* __restrict__ sents) {
    __shared__ __align__(16) float srv[DD];
    int tid = threadIdx.x;
    for (int i = tid; i < DD; i += 256) srv[i] = g_rvar[i];
    __syncthreads();

    int warp = tid >> 5, lane = tid & 31;
    int row = blockIdx.x * 8 + warp;

    const float4* src = reinterpret_cast<const float4*>(sents + (size_t)row * DD);
    float sum = 0.f;
#pragma unroll
    for (int c = 0; c < 4; ++c) {
        int idx4 = c * 32 + lane;   // float4 index in row (128 per row)
        float4 x  = src[idx4];
        float4 rv = *reinterpret_cast<const float4*>(&srv[idx4 * 4]);
        sum += x.x * x.x * rv.x + x.y * x.y * rv.y + x.z * x.z * rv.z + x.w * x.w * rv.w;
        __nv_bfloat162 p0 = __float22bfloat162_rn(make_float2(x.x, x.y));
        __nv_bfloat162 p1 = __float22bfloat162_rn(make_float2(x.z, x.w));
        __nv_bfloat162* dst = reinterpret_cast<__nv_bfloat162*>(&g_Xs[(size_t)row * DD + idx4 * 4]);
        dst[0] = p0;
        dst[1] = p1;
    }
#pragma unroll
    for (int off = 16; off > 0; off >>= 1)
        sum += __shfl_xor_sync(0xffffffffu, sum, off);
    if (lane == 0) g_xq[row] = -0.5f * sum;
}

// =====================================================================
// Kernel 3: density GEMM (copy-only staging) -> E (fragment layout) + dmaxT
// =====================================================================
#define SMSTRIDE 72

__global__ __launch_bounds__(256) void density_kernel() {
    __shared__ __align__(16) __nv_bfloat16 sA[128 * SMSTRIDE];
    __shared__ __align__(16) __nv_bfloat16 sB[128 * SMSTRIDE];
    __shared__ float scb[128];

    int tid  = threadIdx.x;
    int warp = tid >> 5, lane = tid & 31;
    int g = lane >> 2, tg = lane & 3;
    int mbase = blockIdx.x * 128;

    if (tid < 128) scb[tid] = g_colbias[tid];

    float acc[16][4];
#pragma unroll
    for (int n = 0; n < 16; ++n)
#pragma unroll
        for (int k = 0; k < 4; ++k) acc[n][k] = 0.f;

    __syncthreads();

    for (int ko = 0; ko < 8; ++ko) {
        // ---- stage A: 128x64 bf16 pure copies from g_Xs ----
#pragma unroll
        for (int k = 0; k < 4; ++k) {
            int idx = tid + k * 256;         // 1024 uint4 total
            int r = idx >> 3, c8 = idx & 7;
            uint4 va = *reinterpret_cast<const uint4*>(&g_Xs[(size_t)(mbase + r) * DD + ko * 64 + c8 * 8]);
            *reinterpret_cast<uint4*>(&sA[r * SMSTRIDE + c8 * 8]) = va;
        }
        // ---- stage B: 128x64 bf16 from g_Mv ----
#pragma unroll
        for (int k = 0; k < 4; ++k) {
            int idx = tid + k * 256;
            int r = idx >> 3, c8 = idx & 7;
            uint4 vb = *reinterpret_cast<const uint4*>(&g_Mv[(size_t)r * DD + ko * 64 + c8 * 8]);
            *reinterpret_cast<uint4*>(&sB[r * SMSTRIDE + c8 * 8]) = vb;
        }
        __syncthreads();

#pragma unroll
        for (int ks = 0; ks < 4; ++ks) {
            int k0 = ks * 16 + tg * 2;
            uint32_t a0 = *reinterpret_cast<const uint32_t*>(&sA[(warp * 16 + g)     * SMSTRIDE + k0]);
            uint32_t a1 = *reinterpret_cast<const uint32_t*>(&sA[(warp * 16 + g + 8) * SMSTRIDE + k0]);
            uint32_t a2 = *reinterpret_cast<const uint32_t*>(&sA[(warp * 16 + g)     * SMSTRIDE + k0 + 8]);
            uint32_t a3 = *reinterpret_cast<const uint32_t*>(&sA[(warp * 16 + g + 8) * SMSTRIDE + k0 + 8]);
#pragma unroll
            for (int n = 0; n < 16; ++n) {
                uint32_t b0 = *reinterpret_cast<const uint32_t*>(&sB[(n * 8 + g) * SMSTRIDE + k0]);
                uint32_t b1 = *reinterpret_cast<const uint32_t*>(&sB[(n * 8 + g) * SMSTRIDE + k0 + 8]);
                mma_bf16(acc[n][0], acc[n][1], acc[n][2], acc[n][3], a0, a1, a2, a3, b0, b1);
            }
        }
        __syncthreads();
    }

    int r0l = warp * 16 + g;
    int r0 = mbase + r0l;
    int r1 = r0 + 8;
    float xq0 = g_xq[r0], xq1 = g_xq[r1];

    float mx0 = -1e30f, mx1 = -1e30f;
#pragma unroll
    for (int n = 0; n < 16; ++n) {
        int col = n * 8 + tg * 2;
        float cb0 = scb[col], cb1 = scb[col + 1];
        acc[n][0] += cb0; acc[n][1] += cb1;
        acc[n][2] += cb0; acc[n][3] += cb1;
        mx0 = fmaxf(mx0, fmaxf(acc[n][0], acc[n][1]));
        mx1 = fmaxf(mx1, fmaxf(acc[n][2], acc[n][3]));
    }
    mx0 = fmaxf(mx0, __shfl_xor_sync(0xffffffffu, mx0, 1));
    mx0 = fmaxf(mx0, __shfl_xor_sync(0xffffffffu, mx0, 2));
    mx1 = fmaxf(mx1, __shfl_xor_sync(0xffffffffu, mx1, 1));
    mx1 = fmaxf(mx1, __shfl_xor_sync(0xffffffffu, mx1, 2));

    // E fragment write, lane-major: [((l*32+btile)*16 + n)*32 + lane]
    int b = r0 & (BB - 1);
    int l = r0 >> 9;
    int btile = b >> 4;
    uint2* eout = &g_Efrag[((size_t)(l * 32 + btile) * 16) * 32 + lane];
#pragma unroll
    for (int n = 0; n < 16; ++n) {
        __nv_bfloat162 e01 = __floats2bfloat162_rn(fexp(acc[n][0] - mx0), fexp(acc[n][1] - mx0));
        __nv_bfloat162 e23 = __floats2bfloat162_rn(fexp(acc[n][2] - mx1), fexp(acc[n][3] - mx1));
        eout[n * 32] = make_uint2(pk(e01), pk(e23));
    }
    if (tg == 0) {
        g_dmaxT[(size_t)b * LL + l]       = mx0 + xq0;
        g_dmaxT[(size_t)(b + 8) * LL + l] = mx1 + xq1;
    }
}

// =====================================================================
// Kernel 4: forward recurrence — 8-warp n-split tensor-core version (R8).
// =====================================================================
#define ATSTRIDE 136   // bf16 elems per padded row (272 B)
#define PSTRIDE  136

#define OFF_AT    0                         // 34816
#define OFF_P0    34816                     // 4352
#define OFF_P1    (OFF_P0 + 4352)
#define OFF_DMAX  (OFF_P1 + 4352)           // 8192
#define OFF_MK    (OFF_DMAX + 8192)         // 2048
#define OFF_SRN   (OFF_MK + 2048)           // 512
#define OFF_SSUM  (OFF_SRN + 512)           // 512
#define OFF_SM    (OFF_SSUM + 512)          // 64
#define RECUR_SMEM (OFF_SM + 64)

__global__ __launch_bounds__(256) void recur_kernel(const float* __restrict__ masks) {
    extern __shared__ __align__(16) unsigned char dyn[];
    __nv_bfloat16* sAt = reinterpret_cast<__nv_bfloat16*>(dyn + OFF_AT);
    __nv_bfloat16* sp0 = reinterpret_cast<__nv_bfloat16*>(dyn + OFF_P0);
    __nv_bfloat16* sp1 = reinterpret_cast<__nv_bfloat16*>(dyn + OFF_P1);
    float* sdmax = reinterpret_cast<float*>(dyn + OFF_DMAX);
    unsigned char* smk = dyn + OFF_MK;
    float (*srn)[16]  = reinterpret_cast<float (*)[16]>(dyn + OFF_SRN);
    float (*ssum)[16] = reinterpret_cast<float (*)[16]>(dyn + OFF_SSUM);
    float* sM = reinterpret_cast<float*>(dyn + OFF_SM);

    int tid   = threadIdx.x;
    int lane  = tid & 31, w = tid >> 5;     // w in [0,8)
    int btile = blockIdx.x;                  // 0..31
    int g = lane >> 2, tg = lane & 3;

    {
        const uint4* src = reinterpret_cast<const uint4*>(g_At);   // 2048 uint4
        for (int idx = tid; idx < 2048; idx += 256) {
            int j = idx >> 4, c = idx & 15;
            *reinterpret_cast<uint4*>(&sAt[j * ATSTRIDE + c * 8]) = src[idx];
        }
    }
    for (int idx = tid; idx < 2048; idx += 256) {
        int bi = idx >> 7, l = idx & 127;
        sdmax[l * 16 + bi] = g_dmaxT[(size_t)(btile * 16 + bi) * LL + l];
        smk[l * 16 + bi]   = (masks[l * BB + btile * 16 + bi] >= 0.5f) ? 1 : 0;
    }
    __syncthreads();

    // hoist B fragments: warp w covers n-pair group np = w
    int q = lane >> 3, r = lane & 7;
    int rowb = ((q & 2) ? 8 : 0) + r;
    int kofs = (q & 1) ? 8 : 0;
    uint32_t bbase = smem_u32(&sAt[rowb * ATSTRIDE + kofs]);
    uint32_t bf[32];
#pragma unroll
    for (int kt = 0; kt < 8; ++kt) {
        ldmx4(bf[kt * 4 + 0], bf[kt * 4 + 1], bf[kt * 4 + 2], bf[kt * 4 + 3],
              bbase + w * (16 * ATSTRIDE * 2) + kt * 32);
    }

    const uint2* __restrict__ Eb = g_Efrag + (size_t)btile * 512 + lane;

    uint32_t pv01[2], pv23[2];
#pragma unroll
    for (int lt = 0; lt < 2; ++lt) {
        uint2 e = Eb[(2 * w + lt) * 32];
        pv01[lt] = e.x;
        pv23[lt] = e.y;
    }
#pragma unroll
    for (int lt = 0; lt < 2; ++lt) {
        int col = (2 * w + lt) * 8 + 2 * tg;
        *reinterpret_cast<uint32_t*>(&sp0[g * PSTRIDE + col])       = pv01[lt];
        *reinterpret_cast<uint32_t*>(&sp0[(g + 8) * PSTRIDE + col]) = pv23[lt];
    }
    float Mg = LOGPI_INIT + sdmax[g];
    float Mh = LOGPI_INIT + sdmax[g + 8];
    __syncthreads();

    int arow = (lane & 7) + ((lane & 8) ? 8 : 0);
    int akof = (lane & 16) ? 8 : 0;
    uint32_t abase[2];
    abase[0] = smem_u32(&sp0[arow * PSTRIDE + akof]);
    abase[1] = smem_u32(&sp1[arow * PSTRIDE + akof]);

    int buf = 0;
    for (int l = 1; l < LL; ++l) {
        uint32_t af[32];
#pragma unroll
        for (int kt = 0; kt < 8; ++kt)
            ldmx4(af[kt * 4 + 0], af[kt * 4 + 1], af[kt * 4 + 2], af[kt * 4 + 3],
                  abase[buf] + kt * 32);

        const uint2* Ep = Eb + (size_t)l * 16384;
        uint2 ef[2];
#pragma unroll
        for (int lt = 0; lt < 2; ++lt) ef[lt] = Ep[(2 * w + lt) * 32];

        float dm0 = sdmax[l * 16 + g];
        float dm1 = sdmax[l * 16 + g + 8];
        int mk0 = smk[l * 16 + g];
        int mk1 = smk[l * 16 + g + 8];

        float acc[2][4];
#pragma unroll
        for (int n = 0; n < 2; ++n)
#pragma unroll
            for (int k = 0; k < 4; ++k) acc[n][k] = 0.f;

#pragma unroll
        for (int kt = 0; kt < 8; ++kt) {
            uint32_t a0 = af[kt * 4 + 0], a1 = af[kt * 4 + 1];
            uint32_t a2 = af[kt * 4 + 2], a3 = af[kt * 4 + 3];
            const uint32_t* bb = &bf[kt * 4];
            mma_bf16(acc[0][0], acc[0][1], acc[0][2], acc[0][3],
                     a0, a1, a2, a3, bb[0], bb[1]);
            mma_bf16(acc[1][0], acc[1][1], acc[1][2], acc[1][3],
                     a0, a1, a2, a3, bb[2], bb[3]);
        }

#pragma unroll
        for (int lt = 0; lt < 2; ++lt) {
            float2 eg = __bfloat1622float2(upk(ef[lt].x));
            float2 eh = __bfloat1622float2(upk(ef[lt].y));
            uint32_t u01 = pk(__floats2bfloat162_rn(acc[lt][0] * eg.x, acc[lt][1] * eg.y));
            uint32_t u23 = pk(__floats2bfloat162_rn(acc[lt][2] * eh.x, acc[lt][3] * eh.y));
            if (!mk0) u01 = pv01[lt];
            if (!mk1) u23 = pv23[lt];
            pv01[lt] = u01;
            pv23[lt] = u23;
        }
        if (mk0) Mg += dm0;
        if (mk1) Mh += dm1;

        if ((l & 7) == 0) {
            float mg = 1e-30f, mh = 1e-30f;
#pragma unroll
            for (int lt = 0; lt < 2; ++lt) {
                float2 v01 = __bfloat1622float2(upk(pv01[lt]));
                float2 v23 = __bfloat1622float2(upk(pv23[lt]));
                mg = fmaxf(mg, fmaxf(v01.x, v01.y));
                mh = fmaxf(mh, fmaxf(v23.x, v23.y));
            }
            mg = fmaxf(mg, __shfl_xor_sync(0xffffffffu, mg, 1));
            mg = fmaxf(mg, __shfl_xor_sync(0xffffffffu, mg, 2));
            mh = fmaxf(mh, __shfl_xor_sync(0xffffffffu, mh, 1));
            mh = fmaxf(mh, __shfl_xor_sync(0xffffffffu, mh, 2));
            if (tg == 0) { srn[w][g] = mg; srn[w][g + 8] = mh; }
            __syncthreads();
#pragma unroll
            for (int ww = 0; ww < 8; ++ww) {
                mg = fmaxf(mg, srn[ww][g]);
                mh = fmaxf(mh, srn[ww][g + 8]);
            }
            float rg = 1.f / mg, rh = 1.f / mh;
#pragma unroll
            for (int lt = 0; lt < 2; ++lt) {
                float2 v01 = __bfloat1622float2(upk(pv01[lt]));
                float2 v23 = __bfloat1622float2(upk(pv23[lt]));
                pv01[lt] = pk(__floats2bfloat162_rn(v01.x * rg, v01.y * rg));
                pv23[lt] = pk(__floats2bfloat162_rn(v23.x * rh, v23.y * rh));
            }
            Mg += __logf(mg);
            Mh += __logf(mh);
        }

        int nbuf = buf ^ 1;
        {
            __nv_bfloat16* base = nbuf ? sp1 : sp0;
#pragma unroll
            for (int lt = 0; lt < 2; ++lt) {
                int col = (2 * w + lt) * 8 + 2 * tg;
                *reinterpret_cast<uint32_t*>(&base[g * PSTRIDE + col])       = pv01[lt];
                *reinterpret_cast<uint32_t*>(&base[(g + 8) * PSTRIDE + col]) = pv23[lt];
            }
        }
        __syncthreads();
        buf = nbuf;
    }

    float Sg = 0.f, Sh = 0.f;
#pragma unroll
    for (int lt = 0; lt < 2; ++lt) {
        float2 v01 = __bfloat1622float2(upk(pv01[lt]));
        float2 v23 = __bfloat1622float2(upk(pv23[lt]));
        Sg += v01.x + v01.y;
        Sh += v23.x + v23.y;
    }
    Sg += __shfl_xor_sync(0xffffffffu, Sg, 1);
    Sg += __shfl_xor_sync(0xffffffffu, Sg, 2);
    Sh += __shfl_xor_sync(0xffffffffu, Sh, 1);
    Sh += __shfl_xor_sync(0xffffffffu, Sh, 2);
    if (tg == 0) {
        ssum[w][g] = Sg;
        ssum[w][g + 8] = Sh;
        if (w == 0) { sM[g] = Mg; sM[g + 8] = Mh; }
    }
    __syncthreads();
    if (tid < 16) {
        float S = 0.f;
#pragma unroll
        for (int ww = 0; ww < 8; ++ww) S += ssum[ww][tid];
        S = fmaxf(S, 1e-37f);
        g_perb[btile * 16 + tid] = sM[tid] + __logf(S);
    }
}

// =====================================================================
// Kernel 5: deterministic final reduction over 512 batch rows
// =====================================================================
__global__ void finalize_kernel(float* __restrict__ out, int out_size) {
    __shared__ float s[256];
    int t = threadIdx.x;
    s[t] = g_perb[t] + g_perb[t + 256];
    __syncthreads();
    for (int off = 128; off > 0; off >>= 1) {
        if (t < off) s[t] += s[t + off];
        __syncthreads();
    }
    for (int i = t; i < out_size; i += 256)
        if (i != 0) out[i] = 0.f;   // jacobian_loss = 0
    if (t == 0) out[0] = s[0];
}

// =====================================================================
extern "C" void kernel_launch(void* const* d_in, const int* in_sizes, int n_in,
                              void* d_out, int out_size) {
    const float* sents   = (const float*)d_in[0];
    const float* masks   = (const float*)d_in[1];
    const float* tparams = (const float*)d_in[2];
    const float* means   = (const float*)d_in[3];
    const float* var     = (const float*)d_in[4];
    float* out = (float*)d_out;

    cudaFuncSetAttribute(recur_kernel, cudaFuncAttributeMaxDynamicSharedMemorySize, RECUR_SMEM);

    prep_kernel<<<1, 512>>>(tparams, means, var);
    xqcast_kernel<<<LB / 8, 256>>>(sents);
    density_kernel<<<LB / 128, 256>>>();
    recur_kernel<<<32, 256, RECUR_SMEM>>>(masks);
    finalize_kernel<<<1, 256>>>(out, out_size);
}